// round 14
// baseline (speedup 1.0000x reference)
#include <cuda_runtime.h>
#include <cuda_fp16.h>
#include <cstdint>

// Problem constants
#define B_DIM 4096
#define F_DIM 512
#define T_DIM 2048
#define N_TOTAL 8192            // T*D
#define TAU_F 0.2018004745467103f

// GEMM tiling: CTA 128(M) x 256(N), 8 warps in 2(M) x 4(N), warp tile 64x64
// f16 accumulators -> 64 acc regs/thread -> fits occupancy 2.
#define MT 128
#define NT 256
#define KC 64                   // K elements per smem stage
#define NCHUNK 8                // 512/64
#define THREADS 256
#define A_BYTES 16384           // 128 x 64 f16
#define B_BYTES 32768           // 256 x 64 f16
#define STAGE_BYTES (A_BYTES + B_BYTES)      // 49152
#define SM_TOTAL (2 * STAGE_BYTES)           // 98304 -> 2 CTAs/SM
#define EPI_STRIDE 68           // floats; float4-aligned, bank-rotating

// Scratch (device globals: allocation-free rule)
__device__ __half g_W[N_TOTAL * F_DIM];   // softmax(feature_logits), K-major f16
__device__ __half g_X[B_DIM * F_DIM];     // x in f16

// ---------------- helpers ----------------
__device__ __forceinline__ uint32_t smem_u32(const void* p) {
    uint32_t a;
    asm("{ .reg .u64 t; cvta.to.shared.u64 t, %1; cvt.u32.u64 %0, t; }" : "=r"(a) : "l"(p));
    return a;
}
__device__ __forceinline__ uint32_t swz128(uint32_t off) {   // SW128: bits[6:4] ^= bits[9:7]
    return off ^ ((off >> 3) & 0x70);
}
__device__ __forceinline__ void cp_async16(uint32_t dst, const void* src) {
    asm volatile("cp.async.cg.shared.global [%0], [%1], 16;\n" :: "r"(dst), "l"(src) : "memory");
}
__device__ __forceinline__ void cp_commit() { asm volatile("cp.async.commit_group;\n" ::: "memory"); }
template <int N> __device__ __forceinline__ void cp_wait() {
    asm volatile("cp.async.wait_group %0;\n" :: "n"(N) : "memory");
}
__device__ __forceinline__ void ldsm_x4(uint32_t* r, uint32_t addr) {
    asm volatile("ldmatrix.sync.aligned.m8n8.x4.shared.b16 {%0,%1,%2,%3}, [%4];"
                 : "=r"(r[0]), "=r"(r[1]), "=r"(r[2]), "=r"(r[3]) : "r"(addr));
}
// f16 x f16 -> f16 accumulate: D frag = 2 regs (f16x2 pairs)
__device__ __forceinline__ void mma_f16(uint32_t* c, const uint32_t* a, uint32_t b0, uint32_t b1) {
    asm volatile("mma.sync.aligned.m16n8k16.row.col.f16.f16.f16.f16 "
                 "{%0,%1}, {%2,%3,%4,%5}, {%6,%7}, {%0,%1};"
                 : "+r"(c[0]), "+r"(c[1])
                 : "r"(a[0]), "r"(a[1]), "r"(a[2]), "r"(a[3]), "r"(b0), "r"(b1));
}

// ---------------- fused prep kernel ----------------
// blocks [0,1024): convert x -> f16 (8 elems/thread)
// blocks [1024,2048): softmax rows (8 warps/block, one row/warp)
__global__ void __launch_bounds__(256) k_prep(const float* __restrict__ x,
                                              const float* __restrict__ logits) {
    if (blockIdx.x < 1024) {
        int i = (blockIdx.x * 256 + threadIdx.x) * 8;
#pragma unroll
        for (int half = 0; half < 2; half++) {
            float4 v = *reinterpret_cast<const float4*>(x + i + half * 4);
            __half2 lo = __floats2half2_rn(v.x, v.y);
            __half2 hi = __floats2half2_rn(v.z, v.w);
            *reinterpret_cast<uint32_t*>(g_X + i + half * 4)     = *reinterpret_cast<uint32_t*>(&lo);
            *reinterpret_cast<uint32_t*>(g_X + i + half * 4 + 2) = *reinterpret_cast<uint32_t*>(&hi);
        }
    } else {
        int warp = (blockIdx.x - 1024) * 8 + (threadIdx.x >> 5);   // one warp per (t,d) row
        int lane = threadIdx.x & 31;
        const float* row = logits + (size_t)warp * F_DIM;
        float v[16], vmax = -1e30f;
#pragma unroll
        for (int i = 0; i < 16; i++) { v[i] = row[lane + i * 32]; vmax = fmaxf(vmax, v[i]); }
#pragma unroll
        for (int o = 16; o > 0; o >>= 1) vmax = fmaxf(vmax, __shfl_xor_sync(0xFFFFFFFFu, vmax, o));
        float s = 0.f;
#pragma unroll
        for (int i = 0; i < 16; i++) { v[i] = __expf(v[i] - vmax); s += v[i]; }
#pragma unroll
        for (int o = 16; o > 0; o >>= 1) s += __shfl_xor_sync(0xFFFFFFFFu, s, o);
        float inv = __fdividef(1.0f, s);
        __half* out = g_W + (size_t)warp * F_DIM;
#pragma unroll
        for (int i = 0; i < 16; i++) out[lane + i * 32] = __float2half_rn(v[i] * inv);
    }
}

// ---------------- fused GEMM + tree epilogue ----------------
__device__ __forceinline__ void load_stage(uint32_t sbase, int tid, int chunk,
                                           const __half* Abase, const __half* Bbase) {
    uint32_t dst = sbase + (chunk & 1) * STAGE_BYTES;
    const char* srcA = reinterpret_cast<const char*>(Abase) + chunk * (KC * 2);
    const char* srcB = reinterpret_cast<const char*>(Bbase) + chunk * (KC * 2);
#pragma unroll
    for (int i = 0; i < 4; i++) {            // A: 128 rows x 8 x 16B
        int idx = tid + i * THREADS;
        int row = idx >> 3, seg = idx & 7;
        cp_async16(dst + swz128(row * 128 + seg * 16), srcA + row * 1024 + seg * 16);
    }
#pragma unroll
    for (int i = 0; i < 8; i++) {            // B: 256 rows x 8 x 16B
        int idx = tid + i * THREADS;
        int row = idx >> 3, seg = idx & 7;
        cp_async16(dst + A_BYTES + swz128(row * 128 + seg * 16), srcB + row * 1024 + seg * 16);
    }
    cp_commit();
}

__global__ void __launch_bounds__(THREADS, 2)
k_main(const float* __restrict__ thr, const float* __restrict__ leaf, float* __restrict__ out) {
    extern __shared__ char smem[];
    uint32_t sbase = smem_u32(smem);
    int tid = threadIdx.x;
    int wid = tid >> 5, lane = tid & 31;
    int wm = wid & 1, wn = wid >> 1;         // 2x4 warp grid; warp tile 64(M) x 64(N)
    int m0 = blockIdx.x * MT;
    int n0 = blockIdx.y * NT;

    const __half* Abase = g_X + (size_t)m0 * F_DIM;
    const __half* Bbase = g_W + (size_t)n0 * F_DIM;

    load_stage(sbase, tid, 0, Abase, Bbase);
    load_stage(sbase, tid, 1, Abase, Bbase);

    uint32_t acc[4][8][2];                   // [m16 frag][n8 tile][f16x2 pair]
#pragma unroll
    for (int i = 0; i < 4; i++)
#pragma unroll
        for (int j = 0; j < 8; j++) { acc[i][j][0] = 0u; acc[i][j][1] = 0u; }

    int tl = lane & 15;
    int arow0 = wm * 64 + tl;                // A rows; mf in {0..3} adds 16 each
    int brow0 = wn * 64 + tl;                // B rows; tp in {0..3} adds 16 each
    int khalf = (lane >> 4) * 16;            // 16B half select within k16

#pragma unroll 1
    for (int c = 0; c < NCHUNK; c++) {
        if (c == NCHUNK - 1) cp_wait<0>(); else cp_wait<1>();
        __syncthreads();                     // stage c resident for all warps

        uint32_t aB = sbase + (c & 1) * STAGE_BYTES;
        uint32_t bB = aB + A_BYTES;
#pragma unroll
        for (int s = 0; s < 4; s++) {        // 4 x k16 steps per 64-K stage
            int koff = s * 32 + khalf;
            uint32_t a[4][4];
#pragma unroll
            for (int mf = 0; mf < 4; mf++)
                ldsm_x4(a[mf], aB + swz128((arow0 + mf * 16) * 128 + koff));
#pragma unroll
            for (int tp = 0; tp < 4; tp++) { // 2 n8-tiles per B ldmatrix.x4
                uint32_t b[4];
                ldsm_x4(b, bB + swz128((brow0 + tp * 16) * 128 + koff));
#pragma unroll
                for (int mf = 0; mf < 4; mf++) {
                    mma_f16(acc[mf][tp * 2],     a[mf], b[0], b[2]);
                    mma_f16(acc[mf][tp * 2 + 1], a[mf], b[1], b[3]);
                }
            }
        }
        __syncthreads();                     // all warps done reading stage c
        if (c + 2 < NCHUNK) load_stage(sbase, tid, c + 2, Abase, Bbase);
        // load c+2 covered by chunk c+1's compute (sources L2-resident)
    }

    // ---- Epilogue: two 32-row passes (staging reuses freed stage buffers) ----
    int tglob = (n0 + wn * 64) / 4 + tl;
    const float inv_tau = 1.0f / TAU_F;
    float th[4];
#pragma unroll
    for (int d = 0; d < 4; d++) th[d] = thr[tglob * 4 + d];
    float L[16];
    {
        const float4* Lv = reinterpret_cast<const float4*>(leaf + (size_t)tglob * 16);
#pragma unroll
        for (int i = 0; i < 4; i++) {
            float4 v = Lv[i];
            L[i * 4] = v.x; L[i * 4 + 1] = v.y; L[i * 4 + 2] = v.z; L[i * 4 + 3] = v.w;
        }
    }

    float* epi = reinterpret_cast<float*>(smem) + wid * 32 * EPI_STRIDE;
    int grp = lane >> 2, qc = (lane & 3) * 2;

#pragma unroll 1
    for (int pass = 0; pass < 2; pass++) {
#pragma unroll
        for (int mf = 0; mf < 2; mf++) {
            int mfa = pass * 2 + mf;         // acc m16-frag index
#pragma unroll
            for (int nt = 0; nt < 8; nt++) {
                int row = mf * 16 + grp;
                int col = nt * 8 + qc;
                float2 lo = __half22float2(*reinterpret_cast<__half2*>(&acc[mfa][nt][0]));
                float2 hi = __half22float2(*reinterpret_cast<__half2*>(&acc[mfa][nt][1]));
                epi[row * EPI_STRIDE + col]           = lo.x;
                epi[row * EPI_STRIDE + col + 1]       = lo.y;
                epi[(row + 8) * EPI_STRIDE + col]     = hi.x;
                epi[(row + 8) * EPI_STRIDE + col + 1] = hi.y;
            }
        }
        __syncwarp();                         // epi region is warp-private

#pragma unroll
        for (int i = 0; i < 16; i++) {
            int row = (lane >> 4) + 2 * i;    // 32 rows of this pass
            float4 xs = *reinterpret_cast<const float4*>(epi + row * EPI_STRIDE + 4 * tl);
            float p[4];
            float zv[4] = {xs.x, xs.y, xs.z, xs.w};
#pragma unroll
            for (int d = 0; d < 4; d++) {
                float z = (zv[d] - th[d]) * inv_tau;
                float e = __expf(-z);
                p[d] = __fdividef(1.0f, 1.0f + e);
            }
            float g[8];
#pragma unroll
            for (int k = 0; k < 8; k++) g[k] = fmaf(p[3], L[8 + k] - L[k], L[k]);
            float h[4];
#pragma unroll
            for (int k = 0; k < 4; k++) h[k] = fmaf(p[2], g[4 + k] - g[k], g[k]);
            float e2[2];
#pragma unroll
            for (int k = 0; k < 2; k++) e2[k] = fmaf(p[1], h[2 + k] - h[k], h[k]);
            float val = fmaf(p[0], e2[1] - e2[0], e2[0]);
            out[(size_t)(m0 + wm * 64 + pass * 32 + row) * T_DIM + tglob] = val;
        }
        __syncwarp();                         // done reading before pass-2 overwrite
    }
}

// ---------------- launch ----------------
extern "C" void kernel_launch(void* const* d_in, const int* in_sizes, int n_in,
                              void* d_out, int out_size) {
    const float* x      = (const float*)d_in[0];
    const float* logits = (const float*)d_in[1];
    const float* thr    = (const float*)d_in[2];
    const float* leaf   = (const float*)d_in[3];
    float* out = (float*)d_out;

    k_prep<<<2048, 256>>>(x, logits);

    cudaFuncSetAttribute(k_main, cudaFuncAttributeMaxDynamicSharedMemorySize, SM_TOTAL);
    dim3 grid(B_DIM / MT, N_TOTAL / NT);
    k_main<<<grid, THREADS, SM_TOTAL>>>(thr, leaf, out);
}

// round 15
// speedup vs baseline: 2.6219x; 2.6219x over previous
#include <cuda_runtime.h>
#include <cuda_fp16.h>
#include <cstdint>

// Problem constants
#define B_DIM 4096
#define F_DIM 512
#define T_DIM 2048
#define N_TOTAL 8192            // T*D
#define TAU_F 0.2018004745467103f

// GEMM tiling: CTA 128(M) x 256(N), 8 warps in 2(M) x 4(N), warp tile 64x64
// f16 accumulators -> 64 acc regs/thread -> fits occupancy 2.
#define MT 128
#define NT 256
#define KC 64                   // K elements per smem stage
#define NCHUNK 8                // 512/64
#define THREADS 256
#define A_BYTES 16384           // 128 x 64 f16
#define B_BYTES 32768           // 256 x 64 f16
#define STAGE_BYTES (A_BYTES + B_BYTES)      // 49152
#define SM_TOTAL (2 * STAGE_BYTES)           // 98304 -> 2 CTAs/SM
#define EPI_STRIDE 68           // floats; float4-aligned, bank-rotating

// Scratch (device globals: allocation-free rule)
__device__ __half g_W[N_TOTAL * F_DIM];   // softmax(feature_logits), K-major f16
__device__ __half g_X[B_DIM * F_DIM];     // x in f16

// ---------------- helpers ----------------
__device__ __forceinline__ uint32_t smem_u32(const void* p) {
    uint32_t a;
    asm("{ .reg .u64 t; cvta.to.shared.u64 t, %1; cvt.u32.u64 %0, t; }" : "=r"(a) : "l"(p));
    return a;
}
__device__ __forceinline__ uint32_t swz128(uint32_t off) {   // SW128: bits[6:4] ^= bits[9:7]
    return off ^ ((off >> 3) & 0x70);
}
__device__ __forceinline__ void cp_async16(uint32_t dst, const void* src) {
    asm volatile("cp.async.cg.shared.global [%0], [%1], 16;\n" :: "r"(dst), "l"(src) : "memory");
}
__device__ __forceinline__ void cp_commit() { asm volatile("cp.async.commit_group;\n" ::: "memory"); }
template <int N> __device__ __forceinline__ void cp_wait() {
    asm volatile("cp.async.wait_group %0;\n" :: "n"(N) : "memory");
}
__device__ __forceinline__ void ldsm_x4(uint32_t* r, uint32_t addr) {
    asm volatile("ldmatrix.sync.aligned.m8n8.x4.shared.b16 {%0,%1,%2,%3}, [%4];"
                 : "=r"(r[0]), "=r"(r[1]), "=r"(r[2]), "=r"(r[3]) : "r"(addr));
}
// f16 x f16 -> f16 accumulate: D frag = 2 regs (f16x2 pairs)
__device__ __forceinline__ void mma_f16(uint32_t* c, const uint32_t* a, uint32_t b0, uint32_t b1) {
    asm volatile("mma.sync.aligned.m16n8k16.row.col.f16.f16.f16.f16 "
                 "{%0,%1}, {%2,%3,%4,%5}, {%6,%7}, {%0,%1};"
                 : "+r"(c[0]), "+r"(c[1])
                 : "r"(a[0]), "r"(a[1]), "r"(a[2]), "r"(a[3]), "r"(b0), "r"(b1));
}

// ---------------- fused prep kernel ----------------
// blocks [0,1024): convert x -> f16 (8 elems/thread)
// blocks [1024,2048): softmax rows (8 warps/block, one row/warp)
__global__ void __launch_bounds__(256) k_prep(const float* __restrict__ x,
                                              const float* __restrict__ logits) {
    if (blockIdx.x < 1024) {
        int i = (blockIdx.x * 256 + threadIdx.x) * 8;
#pragma unroll
        for (int half = 0; half < 2; half++) {
            float4 v = *reinterpret_cast<const float4*>(x + i + half * 4);
            __half2 lo = __floats2half2_rn(v.x, v.y);
            __half2 hi = __floats2half2_rn(v.z, v.w);
            *reinterpret_cast<uint32_t*>(g_X + i + half * 4)     = *reinterpret_cast<uint32_t*>(&lo);
            *reinterpret_cast<uint32_t*>(g_X + i + half * 4 + 2) = *reinterpret_cast<uint32_t*>(&hi);
        }
    } else {
        int warp = (blockIdx.x - 1024) * 8 + (threadIdx.x >> 5);   // one warp per (t,d) row
        int lane = threadIdx.x & 31;
        const float* row = logits + (size_t)warp * F_DIM;
        float v[16], vmax = -1e30f;
#pragma unroll
        for (int i = 0; i < 16; i++) { v[i] = row[lane + i * 32]; vmax = fmaxf(vmax, v[i]); }
#pragma unroll
        for (int o = 16; o > 0; o >>= 1) vmax = fmaxf(vmax, __shfl_xor_sync(0xFFFFFFFFu, vmax, o));
        float s = 0.f;
#pragma unroll
        for (int i = 0; i < 16; i++) { v[i] = __expf(v[i] - vmax); s += v[i]; }
#pragma unroll
        for (int o = 16; o > 0; o >>= 1) s += __shfl_xor_sync(0xFFFFFFFFu, s, o);
        float inv = __fdividef(1.0f, s);
        __half* out = g_W + (size_t)warp * F_DIM;
#pragma unroll
        for (int i = 0; i < 16; i++) out[lane + i * 32] = __float2half_rn(v[i] * inv);
    }
}

// ---------------- fused GEMM + tree epilogue ----------------
__device__ __forceinline__ void load_stage(uint32_t sbase, int tid, int chunk,
                                           const __half* Abase, const __half* Bbase) {
    uint32_t dst = sbase + (chunk & 1) * STAGE_BYTES;
    const char* srcA = reinterpret_cast<const char*>(Abase) + chunk * (KC * 2);
    const char* srcB = reinterpret_cast<const char*>(Bbase) + chunk * (KC * 2);
#pragma unroll
    for (int i = 0; i < 4; i++) {            // A: 128 rows x 8 x 16B
        int idx = tid + i * THREADS;
        int row = idx >> 3, seg = idx & 7;
        cp_async16(dst + swz128(row * 128 + seg * 16), srcA + row * 1024 + seg * 16);
    }
#pragma unroll
    for (int i = 0; i < 8; i++) {            // B: 256 rows x 8 x 16B
        int idx = tid + i * THREADS;
        int row = idx >> 3, seg = idx & 7;
        cp_async16(dst + A_BYTES + swz128(row * 128 + seg * 16), srcB + row * 1024 + seg * 16);
    }
    cp_commit();
}

// One 32-row epilogue pass: stage two m16 frags to smem, fold trees, write out.
// mfa0/mfa1 and rowoff are compile-time constants => acc indices stay constant
// => accumulators remain in registers (the R14 bug was a runtime index here).
#define EPI_PASS(MFA0, MFA1, ROWOFF)                                                   \
    do {                                                                               \
        _Pragma("unroll")                                                              \
        for (int nt = 0; nt < 8; nt++) {                                               \
            int col = nt * 8 + qc;                                                     \
            float2 lo0 = __half22float2(*reinterpret_cast<__half2*>(&acc[MFA0][nt][0]));\
            float2 hi0 = __half22float2(*reinterpret_cast<__half2*>(&acc[MFA0][nt][1]));\
            float2 lo1 = __half22float2(*reinterpret_cast<__half2*>(&acc[MFA1][nt][0]));\
            float2 hi1 = __half22float2(*reinterpret_cast<__half2*>(&acc[MFA1][nt][1]));\
            epi[grp * EPI_STRIDE + col]            = lo0.x;                            \
            epi[grp * EPI_STRIDE + col + 1]        = lo0.y;                            \
            epi[(grp + 8) * EPI_STRIDE + col]      = hi0.x;                            \
            epi[(grp + 8) * EPI_STRIDE + col + 1]  = hi0.y;                            \
            epi[(grp + 16) * EPI_STRIDE + col]     = lo1.x;                            \
            epi[(grp + 16) * EPI_STRIDE + col + 1] = lo1.y;                            \
            epi[(grp + 24) * EPI_STRIDE + col]     = hi1.x;                            \
            epi[(grp + 24) * EPI_STRIDE + col + 1] = hi1.y;                            \
        }                                                                              \
        __syncwarp();                                                                  \
        _Pragma("unroll")                                                              \
        for (int i = 0; i < 16; i++) {                                                 \
            int row = (lane >> 4) + 2 * i;                                             \
            float4 xs = *reinterpret_cast<const float4*>(epi + row * EPI_STRIDE + 4 * tl);\
            float p[4];                                                                \
            float zv[4] = {xs.x, xs.y, xs.z, xs.w};                                    \
            _Pragma("unroll")                                                          \
            for (int d = 0; d < 4; d++) {                                              \
                float z = (zv[d] - th[d]) * inv_tau;                                   \
                float e = __expf(-z);                                                  \
                p[d] = __fdividef(1.0f, 1.0f + e);                                     \
            }                                                                          \
            float g[8];                                                                \
            _Pragma("unroll")                                                          \
            for (int k = 0; k < 8; k++) g[k] = fmaf(p[3], L[8 + k] - L[k], L[k]);      \
            float h[4];                                                                \
            _Pragma("unroll")                                                          \
            for (int k = 0; k < 4; k++) h[k] = fmaf(p[2], g[4 + k] - g[k], g[k]);      \
            float e2[2];                                                               \
            _Pragma("unroll")                                                          \
            for (int k = 0; k < 2; k++) e2[k] = fmaf(p[1], h[2 + k] - h[k], h[k]);     \
            float val = fmaf(p[0], e2[1] - e2[0], e2[0]);                              \
            out[(size_t)(m0 + wm * 64 + (ROWOFF) + row) * T_DIM + tglob] = val;        \
        }                                                                              \
        __syncwarp();                                                                  \
    } while (0)

__global__ void __launch_bounds__(THREADS, 2)
k_main(const float* __restrict__ thr, const float* __restrict__ leaf, float* __restrict__ out) {
    extern __shared__ char smem[];
    uint32_t sbase = smem_u32(smem);
    int tid = threadIdx.x;
    int wid = tid >> 5, lane = tid & 31;
    int wm = wid & 1, wn = wid >> 1;         // 2x4 warp grid; warp tile 64(M) x 64(N)
    int m0 = blockIdx.x * MT;
    int n0 = blockIdx.y * NT;

    const __half* Abase = g_X + (size_t)m0 * F_DIM;
    const __half* Bbase = g_W + (size_t)n0 * F_DIM;

    load_stage(sbase, tid, 0, Abase, Bbase);
    load_stage(sbase, tid, 1, Abase, Bbase);

    uint32_t acc[4][8][2];                   // [m16 frag][n8 tile][f16x2 pair]
#pragma unroll
    for (int i = 0; i < 4; i++)
#pragma unroll
        for (int j = 0; j < 8; j++) { acc[i][j][0] = 0u; acc[i][j][1] = 0u; }

    int tl = lane & 15;
    int arow0 = wm * 64 + tl;                // A rows; mf in {0..3} adds 16 each
    int brow0 = wn * 64 + tl;                // B rows; tp in {0..3} adds 16 each
    int khalf = (lane >> 4) * 16;            // 16B half select within k16

#pragma unroll 1
    for (int c = 0; c < NCHUNK; c++) {
        if (c == NCHUNK - 1) cp_wait<0>(); else cp_wait<1>();
        __syncthreads();                     // stage c resident for all warps

        uint32_t aB = sbase + (c & 1) * STAGE_BYTES;
        uint32_t bB = aB + A_BYTES;
#pragma unroll
        for (int s = 0; s < 4; s++) {        // 4 x k16 steps per 64-K stage
            int koff = s * 32 + khalf;
            uint32_t a[4][4];
#pragma unroll
            for (int mf = 0; mf < 4; mf++)
                ldsm_x4(a[mf], aB + swz128((arow0 + mf * 16) * 128 + koff));
#pragma unroll
            for (int tp = 0; tp < 4; tp++) { // 2 n8-tiles per B ldmatrix.x4
                uint32_t b[4];
                ldsm_x4(b, bB + swz128((brow0 + tp * 16) * 128 + koff));
#pragma unroll
                for (int mf = 0; mf < 4; mf++) {
                    mma_f16(acc[mf][tp * 2],     a[mf], b[0], b[2]);
                    mma_f16(acc[mf][tp * 2 + 1], a[mf], b[1], b[3]);
                }
            }
        }
        __syncthreads();                     // all warps done reading stage c
        if (c + 2 < NCHUNK) load_stage(sbase, tid, c + 2, Abase, Bbase);
        // load c+2 covered by chunk c+1's compute (sources L2-resident)
    }

    // ---- Epilogue: two fully-unrolled 32-row passes ----
    int tglob = (n0 + wn * 64) / 4 + tl;
    const float inv_tau = 1.0f / TAU_F;
    float th[4];
#pragma unroll
    for (int d = 0; d < 4; d++) th[d] = thr[tglob * 4 + d];
    float L[16];
    {
        const float4* Lv = reinterpret_cast<const float4*>(leaf + (size_t)tglob * 16);
#pragma unroll
        for (int i = 0; i < 4; i++) {
            float4 v = Lv[i];
            L[i * 4] = v.x; L[i * 4 + 1] = v.y; L[i * 4 + 2] = v.z; L[i * 4 + 3] = v.w;
        }
    }

    float* epi = reinterpret_cast<float*>(smem) + wid * 32 * EPI_STRIDE;
    int grp = lane >> 2, qc = (lane & 3) * 2;

    EPI_PASS(0, 1, 0);                       // rows [0,32) of the warp tile
    EPI_PASS(2, 3, 32);                      // rows [32,64)
}

// ---------------- launch ----------------
extern "C" void kernel_launch(void* const* d_in, const int* in_sizes, int n_in,
                              void* d_out, int out_size) {
    const float* x      = (const float*)d_in[0];
    const float* logits = (const float*)d_in[1];
    const float* thr    = (const float*)d_in[2];
    const float* leaf   = (const float*)d_in[3];
    float* out = (float*)d_out;

    k_prep<<<2048, 256>>>(x, logits);

    cudaFuncSetAttribute(k_main, cudaFuncAttributeMaxDynamicSharedMemorySize, SM_TOTAL);
    dim3 grid(B_DIM / MT, N_TOTAL / NT);
    k_main<<<grid, THREADS, SM_TOTAL>>>(thr, leaf, out);
}

// round 16
// speedup vs baseline: 2.7084x; 1.0330x over previous
#include <cuda_runtime.h>
#include <cuda_fp16.h>
#include <cstdint>

// Problem constants
#define B_DIM 4096
#define F_DIM 512
#define T_DIM 2048
#define N_TOTAL 8192            // T*D
#define TAU_F 0.2018004745467103f

// GEMM tiling: CTA 128x128, 8 warps in 4(M) x 2(N), warp tile 32x64
// f16 accumulators (32 regs) + cross-step fragment double-buffering.
#define MT 128
#define NT 128
#define KC 64                   // K elements per smem stage
#define NCHUNK 8                // 512/64
#define NSTAGE 3
#define THREADS 256
#define STAGE_BYTES 32768       // (128+128)*64*2
#define SM_TOTAL (NSTAGE * STAGE_BYTES)      // 98304 -> 2 CTAs/SM
#define EPI_STRIDE 68           // floats; float4-aligned, bank-rotating

// Scratch (device globals: allocation-free rule)
__device__ __half g_W[N_TOTAL * F_DIM];   // softmax(feature_logits), K-major f16
__device__ __half g_X[B_DIM * F_DIM];     // x in f16

// ---------------- helpers ----------------
__device__ __forceinline__ uint32_t smem_u32(const void* p) {
    uint32_t a;
    asm("{ .reg .u64 t; cvta.to.shared.u64 t, %1; cvt.u32.u64 %0, t; }" : "=r"(a) : "l"(p));
    return a;
}
__device__ __forceinline__ uint32_t swz128(uint32_t off) {   // SW128: bits[6:4] ^= bits[9:7]
    return off ^ ((off >> 3) & 0x70);
}
__device__ __forceinline__ void cp_async16(uint32_t dst, const void* src) {
    asm volatile("cp.async.cg.shared.global [%0], [%1], 16;\n" :: "r"(dst), "l"(src) : "memory");
}
__device__ __forceinline__ void cp_commit() { asm volatile("cp.async.commit_group;\n" ::: "memory"); }
template <int N> __device__ __forceinline__ void cp_wait() {
    asm volatile("cp.async.wait_group %0;\n" :: "n"(N) : "memory");
}
__device__ __forceinline__ void ldsm_x4(uint32_t* r, uint32_t addr) {
    asm volatile("ldmatrix.sync.aligned.m8n8.x4.shared.b16 {%0,%1,%2,%3}, [%4];"
                 : "=r"(r[0]), "=r"(r[1]), "=r"(r[2]), "=r"(r[3]) : "r"(addr));
}
// f16 x f16 -> f16 accumulate: D frag = 2 regs (f16x2 pairs)
__device__ __forceinline__ void mma_f16(uint32_t* c, const uint32_t* a, uint32_t b0, uint32_t b1) {
    asm volatile("mma.sync.aligned.m16n8k16.row.col.f16.f16.f16.f16 "
                 "{%0,%1}, {%2,%3,%4,%5}, {%6,%7}, {%0,%1};"
                 : "+r"(c[0]), "+r"(c[1])
                 : "r"(a[0]), "r"(a[1]), "r"(a[2]), "r"(a[3]), "r"(b0), "r"(b1));
}

// ---------------- fused prep kernel ----------------
// blocks [0,1024): convert x -> f16 (8 elems/thread)
// blocks [1024,2048): softmax rows (8 warps/block, one row/warp)
__global__ void __launch_bounds__(256) k_prep(const float* __restrict__ x,
                                              const float* __restrict__ logits) {
    if (blockIdx.x < 1024) {
        int i = (blockIdx.x * 256 + threadIdx.x) * 8;
#pragma unroll
        for (int half = 0; half < 2; half++) {
            float4 v = *reinterpret_cast<const float4*>(x + i + half * 4);
            __half2 lo = __floats2half2_rn(v.x, v.y);
            __half2 hi = __floats2half2_rn(v.z, v.w);
            *reinterpret_cast<uint32_t*>(g_X + i + half * 4)     = *reinterpret_cast<uint32_t*>(&lo);
            *reinterpret_cast<uint32_t*>(g_X + i + half * 4 + 2) = *reinterpret_cast<uint32_t*>(&hi);
        }
    } else {
        int warp = (blockIdx.x - 1024) * 8 + (threadIdx.x >> 5);   // one warp per (t,d) row
        int lane = threadIdx.x & 31;
        const float* row = logits + (size_t)warp * F_DIM;
        float v[16], vmax = -1e30f;
#pragma unroll
        for (int i = 0; i < 16; i++) { v[i] = row[lane + i * 32]; vmax = fmaxf(vmax, v[i]); }
#pragma unroll
        for (int o = 16; o > 0; o >>= 1) vmax = fmaxf(vmax, __shfl_xor_sync(0xFFFFFFFFu, vmax, o));
        float s = 0.f;
#pragma unroll
        for (int i = 0; i < 16; i++) { v[i] = __expf(v[i] - vmax); s += v[i]; }
#pragma unroll
        for (int o = 16; o > 0; o >>= 1) s += __shfl_xor_sync(0xFFFFFFFFu, s, o);
        float inv = __fdividef(1.0f, s);
        __half* out = g_W + (size_t)warp * F_DIM;
#pragma unroll
        for (int i = 0; i < 16; i++) out[lane + i * 32] = __float2half_rn(v[i] * inv);
    }
}

// ---------------- fused GEMM + tree epilogue ----------------
__device__ __forceinline__ void load_stage(uint32_t sbase, int tid, int chunk,
                                           const __half* Abase, const __half* Bbase) {
    uint32_t dst = sbase + (chunk % NSTAGE) * STAGE_BYTES;
    const char* srcA = reinterpret_cast<const char*>(Abase) + chunk * (KC * 2);
    const char* srcB = reinterpret_cast<const char*>(Bbase) + chunk * (KC * 2);
#pragma unroll
    for (int i = 0; i < 4; i++) {            // A: 128 rows x 8 x 16B
        int idx = tid + i * THREADS;
        int row = idx >> 3, seg = idx & 7;
        cp_async16(dst + swz128(row * 128 + seg * 16), srcA + row * 1024 + seg * 16);
    }
#pragma unroll
    for (int i = 0; i < 4; i++) {            // B: 128 rows x 8 x 16B
        int idx = tid + i * THREADS;
        int row = idx >> 3, seg = idx & 7;
        cp_async16(dst + 16384 + swz128(row * 128 + seg * 16), srcB + row * 1024 + seg * 16);
    }
    cp_commit();
}

__global__ void __launch_bounds__(THREADS, 2)
k_main(const float* __restrict__ thr, const float* __restrict__ leaf, float* __restrict__ out) {
    extern __shared__ char smem[];
    uint32_t sbase = smem_u32(smem);
    int tid = threadIdx.x;
    int wid = tid >> 5, lane = tid & 31;
    int wm = wid & 3, wn = wid >> 2;         // 4x2 warp grid; warp tile 32(M) x 64(N)
    int m0 = blockIdx.x * MT;
    int n0 = blockIdx.y * NT;

    const __half* Abase = g_X + (size_t)m0 * F_DIM;
    const __half* Bbase = g_W + (size_t)n0 * F_DIM;

    load_stage(sbase, tid, 0, Abase, Bbase);
    load_stage(sbase, tid, 1, Abase, Bbase);

    uint32_t acc[2][8][2];                   // [m16 frag][n8 tile][f16x2 pair]
#pragma unroll
    for (int i = 0; i < 2; i++)
#pragma unroll
        for (int j = 0; j < 8; j++) { acc[i][j][0] = 0u; acc[i][j][1] = 0u; }

    int tl = lane & 15;
    int arow0 = wm * 32 + tl;                // A rows for mf=0 (mf=1 adds 16)
    int brow0 = wn * 64 + tl;                // B rows for tp=0 (tp adds 16 each)
    int khalf = (lane >> 4) * 16;            // 16B half select within k16

    // Cross-step double-buffered fragments: load step s+1 while MMA-ing step s.
    uint32_t a[2][2][4];                     // [buf][mf][quad]
    uint32_t b[2][4][4];                     // [buf][tp][quad]

#pragma unroll 1
    for (int c = 0; c < NCHUNK; c++) {
        if (c >= NCHUNK - 2) cp_wait<0>(); else cp_wait<1>();
        __syncthreads();                     // stage c ready AND stage c-1 consumers done
        if (c + 2 < NCHUNK) load_stage(sbase, tid, c + 2, Abase, Bbase);

        uint32_t aB = sbase + (c % NSTAGE) * STAGE_BYTES;
        uint32_t bB = aB + 16384;

        // Prologue: fragments for k-step 0
#pragma unroll
        for (int mf = 0; mf < 2; mf++)
            ldsm_x4(a[0][mf], aB + swz128((arow0 + mf * 16) * 128 + khalf));
#pragma unroll
        for (int tp = 0; tp < 4; tp++)
            ldsm_x4(b[0][tp], bB + swz128((brow0 + tp * 16) * 128 + khalf));

#pragma unroll
        for (int s = 0; s < 4; s++) {        // 4 x k16 steps per 64-K stage
            int cur = s & 1, nxt = cur ^ 1;
            if (s < 3) {                     // issue ALL next-step loads first:
                int koff = (s + 1) * 32 + khalf;   // each covered by 16 MMA issues
#pragma unroll
                for (int mf = 0; mf < 2; mf++)
                    ldsm_x4(a[nxt][mf], aB + swz128((arow0 + mf * 16) * 128 + koff));
#pragma unroll
                for (int tp = 0; tp < 4; tp++)
                    ldsm_x4(b[nxt][tp], bB + swz128((brow0 + tp * 16) * 128 + koff));
            }
#pragma unroll
            for (int tp = 0; tp < 4; tp++) { // 16 MMAs on current fragments
                mma_f16(acc[0][tp * 2],     a[cur][0], b[cur][tp][0], b[cur][tp][2]);
                mma_f16(acc[0][tp * 2 + 1], a[cur][0], b[cur][tp][1], b[cur][tp][3]);
                mma_f16(acc[1][tp * 2],     a[cur][1], b[cur][tp][0], b[cur][tp][2]);
                mma_f16(acc[1][tp * 2 + 1], a[cur][1], b[cur][tp][1], b[cur][tp][3]);
            }
        }
    }

    // ---- Epilogue: stage acc -> smem (warp-private), fold trees, write out ----
    __syncthreads();                          // all warps done reading stage buffers
    float* epi = reinterpret_cast<float*>(smem) + wid * 32 * EPI_STRIDE;
    int grp = lane >> 2, qc = (lane & 3) * 2;
#pragma unroll
    for (int mf = 0; mf < 2; mf++)
#pragma unroll
        for (int nt = 0; nt < 8; nt++) {
            int row = mf * 16 + grp;
            int col = nt * 8 + qc;
            float2 lo = __half22float2(*reinterpret_cast<__half2*>(&acc[mf][nt][0]));
            float2 hi = __half22float2(*reinterpret_cast<__half2*>(&acc[mf][nt][1]));
            epi[row * EPI_STRIDE + col]           = lo.x;
            epi[row * EPI_STRIDE + col + 1]       = lo.y;
            epi[(row + 8) * EPI_STRIDE + col]     = hi.x;
            epi[(row + 8) * EPI_STRIDE + col + 1] = hi.y;
        }
    __syncwarp();

    // Each lane owns one tree (lane&15) across 32 rows split by half-warp.
    int tglob = (n0 + wn * 64) / 4 + tl;
    const float inv_tau = 1.0f / TAU_F;
    float th[4];
#pragma unroll
    for (int d = 0; d < 4; d++) th[d] = thr[tglob * 4 + d];
    float L[16];
    {
        const float4* Lv = reinterpret_cast<const float4*>(leaf + (size_t)tglob * 16);
#pragma unroll
        for (int i = 0; i < 4; i++) {
            float4 v = Lv[i];
            L[i * 4] = v.x; L[i * 4 + 1] = v.y; L[i * 4 + 2] = v.z; L[i * 4 + 3] = v.w;
        }
    }

#pragma unroll
    for (int i = 0; i < 16; i++) {
        int row = (lane >> 4) + 2 * i;
        float4 xs = *reinterpret_cast<const float4*>(epi + row * EPI_STRIDE + 4 * tl);
        float p[4];
        float zv[4] = {xs.x, xs.y, xs.z, xs.w};
#pragma unroll
        for (int d = 0; d < 4; d++) {
            float z = (zv[d] - th[d]) * inv_tau;
            float e = __expf(-z);
            p[d] = __fdividef(1.0f, 1.0f + e);
        }
        float g[8];
#pragma unroll
        for (int k = 0; k < 8; k++) g[k] = fmaf(p[3], L[8 + k] - L[k], L[k]);
        float h[4];
#pragma unroll
        for (int k = 0; k < 4; k++) h[k] = fmaf(p[2], g[4 + k] - g[k], g[k]);
        float e2[2];
#pragma unroll
        for (int k = 0; k < 2; k++) e2[k] = fmaf(p[1], h[2 + k] - h[k], h[k]);
        float val = fmaf(p[0], e2[1] - e2[0], e2[0]);
        out[(size_t)(m0 + wm * 32 + row) * T_DIM + tglob] = val;
    }
}

// ---------------- launch ----------------
extern "C" void kernel_launch(void* const* d_in, const int* in_sizes, int n_in,
                              void* d_out, int out_size) {
    const float* x      = (const float*)d_in[0];
    const float* logits = (const float*)d_in[1];
    const float* thr    = (const float*)d_in[2];
    const float* leaf   = (const float*)d_in[3];
    float* out = (float*)d_out;

    k_prep<<<2048, 256>>>(x, logits);

    cudaFuncSetAttribute(k_main, cudaFuncAttributeMaxDynamicSharedMemorySize, SM_TOTAL);
    dim3 grid(B_DIM / MT, N_TOTAL / NT);
    k_main<<<grid, THREADS, SM_TOTAL>>>(thr, leaf, out);
}

// round 17
// speedup vs baseline: 2.7789x; 1.0260x over previous
#include <cuda_runtime.h>
#include <cuda_fp16.h>
#include <cstdint>

// Problem constants
#define B_DIM 4096
#define F_DIM 512
#define T_DIM 2048
#define N_TOTAL 8192            // T*D
#define TAU_F 0.2018004745467103f

// GEMM tiling: CTA 128x128, 8 warps in 4(M) x 2(N), warp tile 32x64
// f16 accumulators (32 regs) + cross-step fragment double-buffering.
#define MT 128
#define NT 128
#define KC 64                   // K elements per smem stage
#define NCHUNK 8                // 512/64
#define NSTAGE 3
#define THREADS 256
#define STAGE_BYTES 32768       // (128+128)*64*2
#define SM_TOTAL (NSTAGE * STAGE_BYTES)      // 98304 -> 2 CTAs/SM
#define EPI_STRIDE 68           // floats; float4-aligned, bank-rotating

// Scratch (device globals: allocation-free rule)
__device__ __half g_W[N_TOTAL * F_DIM];   // softmax(feature_logits), K-major f16
__device__ __half g_X[B_DIM * F_DIM];     // x in f16

// ---------------- helpers ----------------
__device__ __forceinline__ uint32_t smem_u32(const void* p) {
    uint32_t a;
    asm("{ .reg .u64 t; cvta.to.shared.u64 t, %1; cvt.u32.u64 %0, t; }" : "=r"(a) : "l"(p));
    return a;
}
__device__ __forceinline__ uint32_t swz128(uint32_t off) {   // SW128: bits[6:4] ^= bits[9:7]
    return off ^ ((off >> 3) & 0x70);
}
__device__ __forceinline__ void cp_async16(uint32_t dst, const void* src) {
    asm volatile("cp.async.cg.shared.global [%0], [%1], 16;\n" :: "r"(dst), "l"(src) : "memory");
}
__device__ __forceinline__ void cp_commit() { asm volatile("cp.async.commit_group;\n" ::: "memory"); }
template <int N> __device__ __forceinline__ void cp_wait() {
    asm volatile("cp.async.wait_group %0;\n" :: "n"(N) : "memory");
}
__device__ __forceinline__ void ldsm_x4(uint32_t* r, uint32_t addr) {
    asm volatile("ldmatrix.sync.aligned.m8n8.x4.shared.b16 {%0,%1,%2,%3}, [%4];"
                 : "=r"(r[0]), "=r"(r[1]), "=r"(r[2]), "=r"(r[3]) : "r"(addr));
}
// f16 x f16 -> f16 accumulate: D frag = 2 regs (f16x2 pairs)
__device__ __forceinline__ void mma_f16(uint32_t* c, const uint32_t* a, uint32_t b0, uint32_t b1) {
    asm volatile("mma.sync.aligned.m16n8k16.row.col.f16.f16.f16.f16 "
                 "{%0,%1}, {%2,%3,%4,%5}, {%6,%7}, {%0,%1};"
                 : "+r"(c[0]), "+r"(c[1])
                 : "r"(a[0]), "r"(a[1]), "r"(a[2]), "r"(a[3]), "r"(b0), "r"(b1));
}
// sigmoid(z) = 0.5*tanh(z/2) + 0.5 via single MUFU.TANH (sm_75+)
__device__ __forceinline__ float fast_sigmoid(float z) {
    float t;
    asm("tanh.approx.f32 %0, %1;" : "=f"(t) : "f"(z * 0.5f));
    return fmaf(t, 0.5f, 0.5f);
}

// ---------------- fused prep kernel ----------------
// blocks [0,1024): convert x -> f16 (8 elems/thread)
// blocks [1024,2048): softmax rows (8 warps/block, one row/warp)
__global__ void __launch_bounds__(256) k_prep(const float* __restrict__ x,
                                              const float* __restrict__ logits) {
    if (blockIdx.x < 1024) {
        int i = (blockIdx.x * 256 + threadIdx.x) * 8;
#pragma unroll
        for (int half = 0; half < 2; half++) {
            float4 v = *reinterpret_cast<const float4*>(x + i + half * 4);
            __half2 lo = __floats2half2_rn(v.x, v.y);
            __half2 hi = __floats2half2_rn(v.z, v.w);
            *reinterpret_cast<uint32_t*>(g_X + i + half * 4)     = *reinterpret_cast<uint32_t*>(&lo);
            *reinterpret_cast<uint32_t*>(g_X + i + half * 4 + 2) = *reinterpret_cast<uint32_t*>(&hi);
        }
    } else {
        int warp = (blockIdx.x - 1024) * 8 + (threadIdx.x >> 5);   // one warp per (t,d) row
        int lane = threadIdx.x & 31;
        const float* row = logits + (size_t)warp * F_DIM;
        float v[16], vmax = -1e30f;
#pragma unroll
        for (int i = 0; i < 16; i++) { v[i] = row[lane + i * 32]; vmax = fmaxf(vmax, v[i]); }
#pragma unroll
        for (int o = 16; o > 0; o >>= 1) vmax = fmaxf(vmax, __shfl_xor_sync(0xFFFFFFFFu, vmax, o));
        float s = 0.f;
#pragma unroll
        for (int i = 0; i < 16; i++) { v[i] = __expf(v[i] - vmax); s += v[i]; }
#pragma unroll
        for (int o = 16; o > 0; o >>= 1) s += __shfl_xor_sync(0xFFFFFFFFu, s, o);
        float inv = __fdividef(1.0f, s);
        __half* out = g_W + (size_t)warp * F_DIM;
#pragma unroll
        for (int i = 0; i < 16; i++) out[lane + i * 32] = __float2half_rn(v[i] * inv);
    }
}

// ---------------- fused GEMM + tree epilogue ----------------
__device__ __forceinline__ void load_stage(uint32_t sbase, int tid, int chunk,
                                           const __half* Abase, const __half* Bbase) {
    uint32_t dst = sbase + (chunk % NSTAGE) * STAGE_BYTES;
    const char* srcA = reinterpret_cast<const char*>(Abase) + chunk * (KC * 2);
    const char* srcB = reinterpret_cast<const char*>(Bbase) + chunk * (KC * 2);
#pragma unroll
    for (int i = 0; i < 4; i++) {            // A: 128 rows x 8 x 16B
        int idx = tid + i * THREADS;
        int row = idx >> 3, seg = idx & 7;
        cp_async16(dst + swz128(row * 128 + seg * 16), srcA + row * 1024 + seg * 16);
    }
#pragma unroll
    for (int i = 0; i < 4; i++) {            // B: 128 rows x 8 x 16B
        int idx = tid + i * THREADS;
        int row = idx >> 3, seg = idx & 7;
        cp_async16(dst + 16384 + swz128(row * 128 + seg * 16), srcB + row * 1024 + seg * 16);
    }
    cp_commit();
}

__global__ void __launch_bounds__(THREADS, 2)
k_main(const float* __restrict__ thr, const float* __restrict__ leaf, float* __restrict__ out) {
    extern __shared__ char smem[];
    uint32_t sbase = smem_u32(smem);
    int tid = threadIdx.x;
    int wid = tid >> 5, lane = tid & 31;
    int wm = wid & 3, wn = wid >> 2;         // 4x2 warp grid; warp tile 32(M) x 64(N)
    int m0 = blockIdx.x * MT;
    int n0 = blockIdx.y * NT;

    const __half* Abase = g_X + (size_t)m0 * F_DIM;
    const __half* Bbase = g_W + (size_t)n0 * F_DIM;

    load_stage(sbase, tid, 0, Abase, Bbase);
    load_stage(sbase, tid, 1, Abase, Bbase);

    uint32_t acc[2][8][2];                   // [m16 frag][n8 tile][f16x2 pair]
#pragma unroll
    for (int i = 0; i < 2; i++)
#pragma unroll
        for (int j = 0; j < 8; j++) { acc[i][j][0] = 0u; acc[i][j][1] = 0u; }

    int tl = lane & 15;
    int arow0 = wm * 32 + tl;                // A rows for mf=0 (mf=1 adds 16)
    int brow0 = wn * 64 + tl;                // B rows for tp=0 (tp adds 16 each)
    int khalf = (lane >> 4) * 16;            // 16B half select within k16

    // Cross-step double-buffered fragments: load step s+1 while MMA-ing step s.
    uint32_t a[2][2][4];                     // [buf][mf][quad]
    uint32_t b[2][4][4];                     // [buf][tp][quad]

#pragma unroll 1
    for (int c = 0; c < NCHUNK; c++) {
        if (c >= NCHUNK - 2) cp_wait<0>(); else cp_wait<1>();
        __syncthreads();                     // stage c ready AND stage c-1 consumers done
        if (c + 2 < NCHUNK) load_stage(sbase, tid, c + 2, Abase, Bbase);

        uint32_t aB = sbase + (c % NSTAGE) * STAGE_BYTES;
        uint32_t bB = aB + 16384;

        // Prologue: fragments for k-step 0
#pragma unroll
        for (int mf = 0; mf < 2; mf++)
            ldsm_x4(a[0][mf], aB + swz128((arow0 + mf * 16) * 128 + khalf));
#pragma unroll
        for (int tp = 0; tp < 4; tp++)
            ldsm_x4(b[0][tp], bB + swz128((brow0 + tp * 16) * 128 + khalf));

#pragma unroll
        for (int s = 0; s < 4; s++) {        // 4 x k16 steps per 64-K stage
            int cur = s & 1, nxt = cur ^ 1;
            if (s < 3) {                     // issue ALL next-step loads first:
                int koff = (s + 1) * 32 + khalf;   // each covered by 16 MMA issues
#pragma unroll
                for (int mf = 0; mf < 2; mf++)
                    ldsm_x4(a[nxt][mf], aB + swz128((arow0 + mf * 16) * 128 + koff));
#pragma unroll
                for (int tp = 0; tp < 4; tp++)
                    ldsm_x4(b[nxt][tp], bB + swz128((brow0 + tp * 16) * 128 + koff));
            }
#pragma unroll
            for (int tp = 0; tp < 4; tp++) { // 16 MMAs on current fragments
                mma_f16(acc[0][tp * 2],     a[cur][0], b[cur][tp][0], b[cur][tp][2]);
                mma_f16(acc[0][tp * 2 + 1], a[cur][0], b[cur][tp][1], b[cur][tp][3]);
                mma_f16(acc[1][tp * 2],     a[cur][1], b[cur][tp][0], b[cur][tp][2]);
                mma_f16(acc[1][tp * 2 + 1], a[cur][1], b[cur][tp][1], b[cur][tp][3]);
            }
        }
    }

    // ---- Epilogue: stage acc -> smem (warp-private), fold trees, write out ----
    __syncthreads();                          // all warps done reading stage buffers
    float* epi = reinterpret_cast<float*>(smem) + wid * 32 * EPI_STRIDE;
    int grp = lane >> 2, qc = (lane & 3) * 2;
#pragma unroll
    for (int mf = 0; mf < 2; mf++)
#pragma unroll
        for (int nt = 0; nt < 8; nt++) {
            int row = mf * 16 + grp;
            int col = nt * 8 + qc;
            float2 lo = __half22float2(*reinterpret_cast<__half2*>(&acc[mf][nt][0]));
            float2 hi = __half22float2(*reinterpret_cast<__half2*>(&acc[mf][nt][1]));
            epi[row * EPI_STRIDE + col]           = lo.x;
            epi[row * EPI_STRIDE + col + 1]       = lo.y;
            epi[(row + 8) * EPI_STRIDE + col]     = hi.x;
            epi[(row + 8) * EPI_STRIDE + col + 1] = hi.y;
        }
    __syncwarp();

    // Each lane owns one tree (lane&15) across 32 rows split by half-warp.
    int tglob = (n0 + wn * 64) / 4 + tl;
    const float inv_tau = 1.0f / TAU_F;
    float th[4];
#pragma unroll
    for (int d = 0; d < 4; d++) th[d] = thr[tglob * 4 + d];
    float L[16];
    {
        const float4* Lv = reinterpret_cast<const float4*>(leaf + (size_t)tglob * 16);
#pragma unroll
        for (int i = 0; i < 4; i++) {
            float4 v = Lv[i];
            L[i * 4] = v.x; L[i * 4 + 1] = v.y; L[i * 4 + 2] = v.z; L[i * 4 + 3] = v.w;
        }
    }

#pragma unroll
    for (int i = 0; i < 16; i++) {
        int row = (lane >> 4) + 2 * i;
        float4 xs = *reinterpret_cast<const float4*>(epi + row * EPI_STRIDE + 4 * tl);
        float p[4];
        float zv[4] = {xs.x, xs.y, xs.z, xs.w};
#pragma unroll
        for (int d = 0; d < 4; d++)
            p[d] = fast_sigmoid((zv[d] - th[d]) * inv_tau);
        float g[8];
#pragma unroll
        for (int k = 0; k < 8; k++) g[k] = fmaf(p[3], L[8 + k] - L[k], L[k]);
        float h[4];
#pragma unroll
        for (int k = 0; k < 4; k++) h[k] = fmaf(p[2], g[4 + k] - g[k], g[k]);
        float e2[2];
#pragma unroll
        for (int k = 0; k < 2; k++) e2[k] = fmaf(p[1], h[2 + k] - h[k], h[k]);
        float val = fmaf(p[0], e2[1] - e2[0], e2[0]);
        out[(size_t)(m0 + wm * 32 + row) * T_DIM + tglob] = val;
    }
}

// ---------------- launch ----------------
extern "C" void kernel_launch(void* const* d_in, const int* in_sizes, int n_in,
                              void* d_out, int out_size) {
    const float* x      = (const float*)d_in[0];
    const float* logits = (const float*)d_in[1];
    const float* thr    = (const float*)d_in[2];
    const float* leaf   = (const float*)d_in[3];
    float* out = (float*)d_out;

    k_prep<<<2048, 256>>>(x, logits);

    cudaFuncSetAttribute(k_main, cudaFuncAttributeMaxDynamicSharedMemorySize, SM_TOTAL);
    dim3 grid(B_DIM / MT, N_TOTAL / NT);
    k_main<<<grid, THREADS, SM_TOTAL>>>(thr, leaf, out);
}